// round 7
// baseline (speedup 1.0000x reference)
#include <cuda_runtime.h>
#include <cuda_bf16.h>
#include <math.h>
#include <stdint.h>

// ---------------------------------------------------------------------------
// Problem constants
// ---------------------------------------------------------------------------
#define N_NODES 20000
#define N_EDGES 320000
#define TOT_E   (N_EDGES + N_NODES)
#define N_GRAPHS 128
#define NEG_SLOPE 0.2f
#define EPS_F 1e-16f

#define HC1 320   // H=5, C=64
#define HC2 480   // H=5, C=96
#define HC3 32    // H=1, C=32

#define N_BLK ((N_NODES + 255) / 256)   // 79
#define GEMM_GRID 296                   // 148 SMs x 2 blocks

// ---------------------------------------------------------------------------
// Device scratch
// ---------------------------------------------------------------------------
__device__ __align__(16) __nv_bfloat16 g_xq[N_NODES * 64];
__device__ __align__(16) __nv_bfloat16 g_h1[N_NODES * HC1];
__device__ __align__(16) __nv_bfloat16 g_o1[N_NODES * HC1];
__device__ __align__(16) __nv_bfloat16 g_h2[N_NODES * HC2];
__device__ __align__(16) __nv_bfloat16 g_o2[N_NODES * HC2];
__device__ __align__(16) __nv_bfloat16 g_h3[N_NODES * HC3];
__device__ float g_att[6 * N_NODES * 5];
// contiguous zero region: cnt (N_NODES ints) + pool (N_GRAPHS*32 floats)
__device__ int   g_zero[N_NODES + N_GRAPHS * 32];
__device__ int   g_rowptr[N_NODES + 1];
__device__ int   g_cursor[N_NODES];
__device__ int   g_csrc[TOT_E];
__device__ int   g_bsum[N_BLK];

__device__ __forceinline__ uint32_t pack_bf16x2(float lo, float hi) {
    __nv_bfloat162 h2 = __floats2bfloat162_rn(lo, hi);
    return *(uint32_t*)&h2;
}

// ---------------------------------------------------------------------------
// x -> bf16 ; also zeroes the 6 att accumulators (600k floats over 320k thr)
// ---------------------------------------------------------------------------
__global__ void convert_x(const float* __restrict__ x) {
    int i = blockIdx.x * 256 + threadIdx.x;
    if (i < N_NODES * 64 / 4) {
        float4 v = ((const float4*)x)[i];
        uint2 p;
        p.x = pack_bf16x2(v.x, v.y);
        p.y = pack_bf16x2(v.z, v.w);
        ((uint2*)g_xq)[i] = p;
    }
    // zero att accumulators: 600000 floats
    if (2 * i < 6 * N_NODES * 5) {
        g_att[2 * i] = 0.f;
        if (2 * i + 1 < 6 * N_NODES * 5) g_att[2 * i + 1] = 0.f;
    }
}

// ---------------------------------------------------------------------------
// CSR construction
// ---------------------------------------------------------------------------
__global__ void count_kernel(const int* __restrict__ ei) {
    int i = blockIdx.x * blockDim.x + threadIdx.x;
    if (i < N_EDGES) atomicAdd(&g_zero[ei[N_EDGES + i]], 1);
}

__global__ void scan1_kernel() {
    int i = blockIdx.x * 256 + threadIdx.x;
    int lane = threadIdx.x & 31, w = threadIdx.x >> 5;
    int x = (i < N_NODES) ? (g_zero[i] + 1) : 0;
#pragma unroll
    for (int o = 1; o < 32; o <<= 1) {
        int t = __shfl_up_sync(0xffffffffu, x, o);
        if (lane >= o) x += t;
    }
    __shared__ int wsum[8];
    if (lane == 31) wsum[w] = x;
    __syncthreads();
    if (w == 0) {
        int s = (lane < 8) ? wsum[lane] : 0;
#pragma unroll
        for (int o = 1; o < 8; o <<= 1) {
            int t = __shfl_up_sync(0xffffffffu, s, o);
            if (lane >= o) s += t;
        }
        if (lane < 8) wsum[lane] = s;
    }
    __syncthreads();
    int incl = x + ((w > 0) ? wsum[w - 1] : 0);
    if (i < N_NODES) g_rowptr[i + 1] = incl;
    if (threadIdx.x == 255) g_bsum[blockIdx.x] = incl;
}

__global__ void scan3_kernel() {
    __shared__ int s_off;
    int tid = threadIdx.x, lane = tid & 31;
    if (tid < 32) {
        int off = 0;
        for (int j = lane; j < blockIdx.x; j += 32) off += g_bsum[j];
#pragma unroll
        for (int o = 16; o > 0; o >>= 1)
            off += __shfl_xor_sync(0xffffffffu, off, o);
        if (lane == 0) s_off = off;
    }
    __syncthreads();
    int i = blockIdx.x * 256 + tid;
    if (i == 0) g_rowptr[0] = 0;
    if (i < N_NODES) {
        int incl = g_rowptr[i + 1] + s_off;
        g_rowptr[i + 1] = incl;
        g_cursor[i] = incl - (g_zero[i] + 1);
    }
}

__global__ void scatter_kernel(const int* __restrict__ ei) {
    int i = blockIdx.x * blockDim.x + threadIdx.x;
    if (i >= TOT_E) return;
    int src, dst;
    if (i < N_EDGES) { src = ei[i]; dst = ei[N_EDGES + i]; }
    else             { src = dst = i - N_EDGES; }
    int pos = atomicAdd(&g_cursor[dst], 1);
    g_csrc[pos] = src;
}

// ---------------------------------------------------------------------------
// Persistent bf16 GEMM + fused attention-score epilogue.
// C[N,M](bf16) = A[N,K](bf16) * B[M,K]^T(fp32→bf16)
// BM=128, BN=128, BK=32; 8 warps (4M x 2N), warp tile 32x64; grid-strided tiles.
// ---------------------------------------------------------------------------
__global__ void __launch_bounds__(256, 2)
gemm_att(const __nv_bfloat16* __restrict__ A, const float* __restrict__ B,
         __nv_bfloat16* __restrict__ C,
         const float* __restrict__ att_src, const float* __restrict__ att_dst,
         float* __restrict__ asrc, float* __restrict__ adst,
         int N, int M, int K, int H, int Cc) {
    const int BM = 128, BN = 128, BK = 32, BK2 = 16;
    __shared__ uint32_t As[2][BM][BK2 + 2];
    __shared__ uint32_t Bs[2][BN][BK2 + 2];

    int tid  = threadIdx.x;
    int lane = tid & 31;
    int wid  = tid >> 5;
    int wr = (wid & 3) * 32;
    int wc = (wid >> 2) * 64;
    int gid = lane >> 2;
    int tig = lane & 3;

    const uint4  zu4 = make_uint4(0, 0, 0, 0);
    const float4 zf4 = make_float4(0.f, 0.f, 0.f, 0.f);
    int ar[2], aq[2], br[4], bq[4];
#pragma unroll
    for (int l = 0; l < 2; l++) { int idx = tid + l * 256; ar[l] = idx >> 2; aq[l] = idx & 3; }
#pragma unroll
    for (int l = 0; l < 4; l++) { int idx = tid + l * 256; br[l] = idx >> 3; bq[l] = idx & 7; }

    int tilesX = (M + BN - 1) / BN;
    int tilesY = (N + BM - 1) / BM;
    int ntiles = tilesX * tilesY;

    for (int t = blockIdx.x; t < ntiles; t += gridDim.x) {
        int blockCol = (t % tilesX) * BN;
        int blockRow = (t / tilesX) * BM;

        uint4  va[2];
        float4 vb[4];

        auto loadTile = [&](int k0) {
#pragma unroll
            for (int l = 0; l < 2; l++)
                va[l] = (blockRow + ar[l] < N)
                      ? *(const uint4*)(A + (size_t)(blockRow + ar[l]) * K + k0 + aq[l] * 8) : zu4;
#pragma unroll
            for (int l = 0; l < 4; l++)
                vb[l] = (blockCol + br[l] < M)
                      ? *(const float4*)(B + (size_t)(blockCol + br[l]) * K + k0 + bq[l] * 4) : zf4;
        };
        auto storeTile = [&](int buf) {
#pragma unroll
            for (int l = 0; l < 2; l++) {
                As[buf][ar[l]][aq[l] * 4]     = va[l].x;
                As[buf][ar[l]][aq[l] * 4 + 1] = va[l].y;
                As[buf][ar[l]][aq[l] * 4 + 2] = va[l].z;
                As[buf][ar[l]][aq[l] * 4 + 3] = va[l].w;
            }
#pragma unroll
            for (int l = 0; l < 4; l++) {
                Bs[buf][br[l]][bq[l] * 2]     = pack_bf16x2(vb[l].x, vb[l].y);
                Bs[buf][br[l]][bq[l] * 2 + 1] = pack_bf16x2(vb[l].z, vb[l].w);
            }
        };

        float acc[2][8][4];
#pragma unroll
        for (int mt = 0; mt < 2; mt++)
#pragma unroll
            for (int nt = 0; nt < 8; nt++)
#pragma unroll
                for (int i = 0; i < 4; i++) acc[mt][nt][i] = 0.f;

        loadTile(0);
        storeTile(0);
        __syncthreads();

        int buf = 0;
        for (int k0 = BK; k0 <= K; k0 += BK) {
            bool has = (k0 < K);
            if (has) loadTile(k0);

#pragma unroll
            for (int ks = 0; ks < 2; ks++) {
                int kb = ks * 8;
                uint32_t a[2][4], b[8][2];
#pragma unroll
                for (int mt = 0; mt < 2; mt++) {
                    int r0 = wr + mt * 16;
                    a[mt][0] = As[buf][r0 + gid    ][kb + tig    ];
                    a[mt][1] = As[buf][r0 + gid + 8][kb + tig    ];
                    a[mt][2] = As[buf][r0 + gid    ][kb + tig + 4];
                    a[mt][3] = As[buf][r0 + gid + 8][kb + tig + 4];
                }
#pragma unroll
                for (int nt = 0; nt < 8; nt++) {
                    int n0 = wc + nt * 8 + gid;
                    b[nt][0] = Bs[buf][n0][kb + tig    ];
                    b[nt][1] = Bs[buf][n0][kb + tig + 4];
                }
#pragma unroll
                for (int mt = 0; mt < 2; mt++)
#pragma unroll
                    for (int nt = 0; nt < 8; nt++) {
                        asm volatile(
                            "mma.sync.aligned.m16n8k16.row.col.f32.bf16.bf16.f32 "
                            "{%0,%1,%2,%3}, {%4,%5,%6,%7}, {%8,%9}, {%0,%1,%2,%3};"
                            : "+f"(acc[mt][nt][0]), "+f"(acc[mt][nt][1]),
                              "+f"(acc[mt][nt][2]), "+f"(acc[mt][nt][3])
                            : "r"(a[mt][0]), "r"(a[mt][1]), "r"(a[mt][2]), "r"(a[mt][3]),
                              "r"(b[nt][0]), "r"(b[nt][1]));
                    }
            }

            if (has) storeTile(buf ^ 1);
            __syncthreads();
            buf ^= 1;
        }

        // ---- store C + att partials ----
        int h_first = (blockCol + wc) / Cc;
        float psrc[2][2][2] = {};
        float pdst[2][2][2] = {};

#pragma unroll
        for (int mt = 0; mt < 2; mt++) {
#pragma unroll
            for (int nt = 0; nt < 8; nt++) {
                int r0 = blockRow + wr + mt * 16 + gid;
                int c0 = blockCol + wc + nt * 8 + tig * 2;
                if (c0 < M) {
                    if (r0 < N)
                        *(uint32_t*)(C + (size_t)r0 * M + c0) =
                            pack_bf16x2(acc[mt][nt][0], acc[mt][nt][1]);
                    if (r0 + 8 < N)
                        *(uint32_t*)(C + (size_t)(r0 + 8) * M + c0) =
                            pack_bf16x2(acc[mt][nt][2], acc[mt][nt][3]);
                    int hb = (blockCol + wc + nt * 8) / Cc - h_first;
                    float a0 = att_src[c0], a1 = att_src[c0 + 1];
                    float d0 = att_dst[c0], d1 = att_dst[c0 + 1];
                    psrc[mt][0][hb] += acc[mt][nt][0] * a0 + acc[mt][nt][1] * a1;
                    psrc[mt][1][hb] += acc[mt][nt][2] * a0 + acc[mt][nt][3] * a1;
                    pdst[mt][0][hb] += acc[mt][nt][0] * d0 + acc[mt][nt][1] * d1;
                    pdst[mt][1][hb] += acc[mt][nt][2] * d0 + acc[mt][nt][3] * d1;
                }
            }
        }
#pragma unroll
        for (int mt = 0; mt < 2; mt++)
#pragma unroll
            for (int hf = 0; hf < 2; hf++)
#pragma unroll
                for (int bk = 0; bk < 2; bk++) {
                    float s = psrc[mt][hf][bk], d = pdst[mt][hf][bk];
                    s += __shfl_xor_sync(0xffffffffu, s, 1);
                    s += __shfl_xor_sync(0xffffffffu, s, 2);
                    d += __shfl_xor_sync(0xffffffffu, d, 1);
                    d += __shfl_xor_sync(0xffffffffu, d, 2);
                    psrc[mt][hf][bk] = s; pdst[mt][hf][bk] = d;
                }
        if (tig == 0) {
#pragma unroll
            for (int mt = 0; mt < 2; mt++)
#pragma unroll
                for (int hf = 0; hf < 2; hf++) {
                    int row = blockRow + wr + mt * 16 + gid + hf * 8;
                    if (row >= N) continue;
#pragma unroll
                    for (int bk = 0; bk < 2; bk++) {
                        int hidx = h_first + bk;
                        if (hidx < H) {
                            atomicAdd(&asrc[row * H + hidx], psrc[mt][hf][bk]);
                            atomicAdd(&adst[row * H + hidx], pdst[mt][hf][bk]);
                        }
                    }
                }
        }
        __syncthreads();
    }
}

// ---------------------------------------------------------------------------
// GAT aggregation, H=5. Fast path deg<=32: warp-0 softmax, one sync.
// ---------------------------------------------------------------------------
template<int C>
__global__ void __launch_bounds__(192)
gat_agg5(const __nv_bfloat16* __restrict__ hfeat,
         const float* __restrict__ asrc,
         const float* __restrict__ adst,
         const float* __restrict__ bias,
         __nv_bfloat16* __restrict__ out) {
    const int HC = 5 * C, NC4 = HC / 4;
    const int EMAX = 128;
    __shared__ float s_w[EMAX * 5];
    __shared__ int   s_src[EMAX];
    __shared__ float s_m[5], s_iz[5];

    int v = blockIdx.x;
    int tid = threadIdx.x, lane = tid & 31, wid = tid >> 5;
    int base = g_rowptr[v];
    int deg = g_rowptr[v + 1] - base;

    float4 acc = make_float4(0.f, 0.f, 0.f, 0.f);
    int head = (tid * 4) / C;

    if (deg <= 32) {
        if (wid == 0) {
            int s = (lane < deg) ? g_csrc[base + lane] : 0;
            if (lane < deg) s_src[lane] = s;
#pragma unroll
            for (int h = 0; h < 5; h++) {
                float e = -INFINITY;
                if (lane < deg) {
                    e = asrc[s * 5 + h] + adst[v * 5 + h];
                    e = (e > 0.f) ? e : NEG_SLOPE * e;
                }
                float m = e;
#pragma unroll
                for (int o = 16; o > 0; o >>= 1)
                    m = fmaxf(m, __shfl_xor_sync(0xffffffffu, m, o));
                float ex = (lane < deg) ? __expf(e - m) : 0.f;
                float z = ex;
#pragma unroll
                for (int o = 16; o > 0; o >>= 1)
                    z += __shfl_xor_sync(0xffffffffu, z, o);
                if (lane < deg) s_w[lane * 5 + h] = ex / (z + EPS_F);
            }
        }
        __syncthreads();
        if (tid < NC4) {
#pragma unroll 2
            for (int j = 0; j < deg; j++) {
                const uint2* hp = (const uint2*)(hfeat + (size_t)s_src[j] * HC);
                float w = s_w[j * 5 + head];
                uint2 hv = hp[tid];
                float2 lo = __bfloat1622float2(*(__nv_bfloat162*)&hv.x);
                float2 hi = __bfloat1622float2(*(__nv_bfloat162*)&hv.y);
                acc.x += w * lo.x; acc.y += w * lo.y;
                acc.z += w * hi.x; acc.w += w * hi.y;
            }
        }
    } else {
        // fallback: 3-phase with global reads (rare)
        if (wid < 5) {
            int h = wid;
            float ad = adst[v * 5 + h];
            float m = -INFINITY;
            for (int j = lane; j < deg; j += 32) {
                int s = g_csrc[base + j];
                float e = asrc[s * 5 + h] + ad;
                e = (e > 0.f) ? e : NEG_SLOPE * e;
                m = fmaxf(m, e);
            }
#pragma unroll
            for (int o = 16; o > 0; o >>= 1)
                m = fmaxf(m, __shfl_xor_sync(0xffffffffu, m, o));
            float z = 0.f;
            for (int j = lane; j < deg; j += 32) {
                int s = g_csrc[base + j];
                float e = asrc[s * 5 + h] + ad;
                e = (e > 0.f) ? e : NEG_SLOPE * e;
                z += __expf(e - m);
            }
#pragma unroll
            for (int o = 16; o > 0; o >>= 1)
                z += __shfl_xor_sync(0xffffffffu, z, o);
            if (lane == 0) { s_m[h] = m; s_iz[h] = 1.f / (z + EPS_F); }
        }
        __syncthreads();
        for (int j0 = 0; j0 < deg; j0 += EMAX) {
            int ch = min(EMAX, deg - j0);
            for (int idx = tid; idx < ch * 5; idx += 192) {
                int j = idx / 5, hh = idx - j * 5;
                int s = g_csrc[base + j0 + j];
                if (hh == 0) s_src[j] = s;
                float e = asrc[s * 5 + hh] + adst[v * 5 + hh];
                e = (e > 0.f) ? e : NEG_SLOPE * e;
                s_w[j * 5 + hh] = __expf(e - s_m[hh]) * s_iz[hh];
            }
            __syncthreads();
            if (tid < NC4) {
                for (int j = 0; j < ch; j++) {
                    const uint2* hp = (const uint2*)(hfeat + (size_t)s_src[j] * HC);
                    float w = s_w[j * 5 + head];
                    uint2 hv = hp[tid];
                    float2 lo = __bfloat1622float2(*(__nv_bfloat162*)&hv.x);
                    float2 hi = __bfloat1622float2(*(__nv_bfloat162*)&hv.y);
                    acc.x += w * lo.x; acc.y += w * lo.y;
                    acc.z += w * hi.x; acc.w += w * hi.y;
                }
            }
            __syncthreads();
        }
    }

    if (tid < NC4) {
        float4 b = ((const float4*)bias)[tid];
        uint2 o;
        o.x = pack_bf16x2(fmaxf(acc.x + b.x, 0.f), fmaxf(acc.y + b.y, 0.f));
        o.y = pack_bf16x2(fmaxf(acc.z + b.z, 0.f), fmaxf(acc.w + b.w, 0.f));
        ((uint2*)(out + (size_t)v * HC))[tid] = o;
    }
}

// ---------------------------------------------------------------------------
// GAT aggregation, H=1, C=32 + fused global_add_pool. warp per node.
// ---------------------------------------------------------------------------
__global__ void __launch_bounds__(256)
gat_agg1_pool(const __nv_bfloat16* __restrict__ hfeat,
              const float* __restrict__ asrc,
              const float* __restrict__ adst,
              const float* __restrict__ bias,
              const int* __restrict__ batch) {
    int wid = threadIdx.x >> 5, lane = threadIdx.x & 31;
    int v = blockIdx.x * 8 + wid;
    if (v >= N_NODES) return;
    int base = g_rowptr[v];
    int deg = g_rowptr[v + 1] - base;
    float ad = adst[v];
    float* pool = (float*)(g_zero + N_NODES);

    float m = -INFINITY;
    for (int j = lane; j < deg; j += 32) {
        int s = g_csrc[base + j];
        float e = asrc[s] + ad;
        e = (e > 0.f) ? e : NEG_SLOPE * e;
        m = fmaxf(m, e);
    }
#pragma unroll
    for (int o = 16; o > 0; o >>= 1)
        m = fmaxf(m, __shfl_xor_sync(0xffffffffu, m, o));
    float z = 0.f;
    for (int j = lane; j < deg; j += 32) {
        int s = g_csrc[base + j];
        float e = asrc[s] + ad;
        e = (e > 0.f) ? e : NEG_SLOPE * e;
        z += __expf(e - m);
    }
#pragma unroll
    for (int o = 16; o > 0; o >>= 1)
        z += __shfl_xor_sync(0xffffffffu, z, o);
    float iz = 1.f / (z + EPS_F);

    float acc = 0.f;
#pragma unroll 2
    for (int j = 0; j < deg; j++) {
        int s = g_csrc[base + j];
        float e = asrc[s] + ad;
        e = (e > 0.f) ? e : NEG_SLOPE * e;
        float w = __expf(e - m) * iz;
        acc += w * __bfloat162float(hfeat[(size_t)s * 32 + lane]);
    }
    float o = fmaxf(acc + bias[lane], 0.f);
    atomicAdd(&pool[batch[v] * 32 + lane], o);
}

// ---------------------------------------------------------------------------
// MLP head
// ---------------------------------------------------------------------------
__global__ void mlp_kernel(const float* __restrict__ lin_w,
                           const float* __restrict__ lin_b,
                           const float* __restrict__ lin2_w,
                           const float* __restrict__ lin2_b,
                           float* __restrict__ out) {
    int g = blockIdx.x;
    __shared__ float sg[32];
    __shared__ float sred[256];
    int tid = threadIdx.x;
    const float* pool = (const float*)(g_zero + N_NODES);
    if (tid < 32) sg[tid] = pool[g * 32 + tid];
    __syncthreads();
    float partial = 0.f;
    for (int u = tid; u < 1024; u += 256) {
        float d = lin_b[u];
        const float* wr = lin_w + u * 32;
#pragma unroll
        for (int c = 0; c < 32; c++) d += sg[c] * wr[c];
        d = fmaxf(d, 0.f);
        partial += d * lin2_w[u];
    }
    sred[tid] = partial;
    __syncthreads();
    for (int s = 128; s > 0; s >>= 1) {
        if (tid < s) sred[tid] += sred[tid + s];
        __syncthreads();
    }
    if (tid == 0) {
        float v = sred[0] + lin2_b[0];
        out[g] = 1.f / (1.f + __expf(-v));
    }
}

// ---------------------------------------------------------------------------
// launch
// ---------------------------------------------------------------------------
extern "C" void kernel_launch(void* const* d_in, const int* in_sizes, int n_in,
                              void* d_out, int out_size) {
    const float* x        = (const float*)d_in[0];
    const float* W1       = (const float*)d_in[1];
    const float* att_s1   = (const float*)d_in[2];
    const float* att_d1   = (const float*)d_in[3];
    const float* b1       = (const float*)d_in[4];
    const float* W2       = (const float*)d_in[5];
    const float* att_s2   = (const float*)d_in[6];
    const float* att_d2   = (const float*)d_in[7];
    const float* b2       = (const float*)d_in[8];
    const float* W3       = (const float*)d_in[9];
    const float* att_s3   = (const float*)d_in[10];
    const float* att_d3   = (const float*)d_in[11];
    const float* b3       = (const float*)d_in[12];
    const float* lin_w    = (const float*)d_in[13];
    const float* lin_b    = (const float*)d_in[14];
    const float* lin2_w   = (const float*)d_in[15];
    const float* lin2_b   = (const float*)d_in[16];
    const int*   ei       = (const int*)d_in[17];
    const int*   batch    = (const int*)d_in[18];
    float* out = (float*)d_out;

    __nv_bfloat16 *xq, *h1, *o1, *h2, *o2, *h3;
    float *attbuf;
    int *zreg;
    cudaGetSymbolAddress((void**)&xq, g_xq);
    cudaGetSymbolAddress((void**)&h1, g_h1);
    cudaGetSymbolAddress((void**)&o1, g_o1);
    cudaGetSymbolAddress((void**)&h2, g_h2);
    cudaGetSymbolAddress((void**)&o2, g_o2);
    cudaGetSymbolAddress((void**)&h3, g_h3);
    cudaGetSymbolAddress((void**)&attbuf, g_att);
    cudaGetSymbolAddress((void**)&zreg, g_zero);

    float* as1 = attbuf;                    float* ad1 = attbuf + N_NODES * 5;
    float* as2 = attbuf + 2 * N_NODES * 5;  float* ad2 = attbuf + 3 * N_NODES * 5;
    float* as3 = attbuf + 4 * N_NODES * 5;  float* ad3 = attbuf + 5 * N_NODES * 5;

    static cudaStream_t s_cs = nullptr;
    static cudaEvent_t ev_fork = nullptr, ev_join = nullptr;
    if (!s_cs) {
        cudaStreamCreateWithFlags(&s_cs, cudaStreamNonBlocking);
        cudaEventCreateWithFlags(&ev_fork, cudaEventDisableTiming);
        cudaEventCreateWithFlags(&ev_join, cudaEventDisableTiming);
    }

    // ---- fork: CSR prefix (without scatter) on side stream ----
    // submission order tuned so ncu -s 5 profiles gemm_att (launch #6):
    // memset(1) count(2) scan1(3) scan3(4) convert_x(5) gemm1(6) scatter(7) ...
    cudaEventRecord(ev_fork, 0);
    cudaStreamWaitEvent(s_cs, ev_fork, 0);
    cudaMemsetAsync(zreg, 0, (N_NODES + N_GRAPHS * 32) * sizeof(int), s_cs);  // #1
    count_kernel<<<(N_EDGES + 255) / 256, 256, 0, s_cs>>>(ei);                // #2
    scan1_kernel<<<N_BLK, 256, 0, s_cs>>>();                                  // #3
    scan3_kernel<<<N_BLK, 256, 0, s_cs>>>();                                  // #4

    // ---- main: convert + GEMM1 ----
    convert_x<<<(N_NODES * 64 / 4 + 255) / 256, 256>>>(x);                    // #5
    gemm_att<<<GEMM_GRID, 256>>>(xq, W1, h1, att_s1, att_d1, as1, ad1,        // #6
                                 N_NODES, HC1, 64, 5, 64);

    // ---- side: scatter, then join ----
    scatter_kernel<<<(TOT_E + 255) / 256, 256, 0, s_cs>>>(ei);                // #7
    cudaEventRecord(ev_join, s_cs);

    // ---- main chain ----
    cudaStreamWaitEvent(0, ev_join, 0);
    gat_agg5<64><<<N_NODES, 192>>>(h1, as1, ad1, b1, o1);
    gemm_att<<<GEMM_GRID, 256>>>(o1, W2, h2, att_s2, att_d2, as2, ad2,
                                 N_NODES, HC2, HC1, 5, 96);
    gat_agg5<96><<<N_NODES, 192>>>(h2, as2, ad2, b2, o2);
    gemm_att<<<GEMM_GRID, 256>>>(o2, W3, h3, att_s3, att_d3, as3, ad3,
                                 N_NODES, HC3, HC2, 1, 32);
    gat_agg1_pool<<<(N_NODES + 7) / 8, 256>>>(h3, as3, ad3, b3, batch);
    mlp_kernel<<<N_GRAPHS, 256>>>(lin_w, lin_b, lin2_w, lin2_b, out);
}

// round 8
// speedup vs baseline: 1.1356x; 1.1356x over previous
#include <cuda_runtime.h>
#include <cuda_bf16.h>
#include <math.h>
#include <stdint.h>

// ---------------------------------------------------------------------------
// Problem constants
// ---------------------------------------------------------------------------
#define N_NODES 20000
#define N_EDGES 320000
#define TOT_E   (N_EDGES + N_NODES)
#define N_GRAPHS 128
#define NEG_SLOPE 0.2f
#define EPS_F 1e-16f

#define HC1 320   // H=5, C=64
#define HC2 480   // H=5, C=96
#define HC3 32    // H=1, C=32

#define N_BLK ((N_NODES + 255) / 256)   // 79

// ---------------------------------------------------------------------------
// Device scratch
// ---------------------------------------------------------------------------
__device__ __align__(16) __nv_bfloat16 g_xq[N_NODES * 64];
__device__ __align__(16) __nv_bfloat16 g_w1q[HC1 * 64];
__device__ __align__(16) __nv_bfloat16 g_w2q[HC2 * HC1];
__device__ __align__(16) __nv_bfloat16 g_w3q[HC3 * HC2];
__device__ __align__(16) __nv_bfloat16 g_h1[N_NODES * HC1];
__device__ __align__(16) __nv_bfloat16 g_o1[N_NODES * HC1];
__device__ __align__(16) __nv_bfloat16 g_h2[N_NODES * HC2];
__device__ __align__(16) __nv_bfloat16 g_o2[N_NODES * HC2];
__device__ __align__(16) __nv_bfloat16 g_h3[N_NODES * HC3];
__device__ float g_att[6 * N_NODES * 5];
// contiguous zero region: cnt (N_NODES ints) + pool (N_GRAPHS*32 floats)
__device__ int   g_zero[N_NODES + N_GRAPHS * 32];
__device__ int   g_rowptr[N_NODES + 1];
__device__ int   g_cursor[N_NODES];
__device__ int   g_csrc[TOT_E];
__device__ int   g_bsum[N_BLK];

__device__ __forceinline__ uint32_t pack_bf16x2(float lo, float hi) {
    __nv_bfloat162 h2 = __floats2bfloat162_rn(lo, hi);
    return *(uint32_t*)&h2;
}

// ---------------------------------------------------------------------------
// prep: x -> bf16, W1/2/3 -> bf16, zero att accumulators
// ---------------------------------------------------------------------------
#define W1Q4 (HC1 * 64 / 4)       // 5120
#define W2Q4 (HC2 * HC1 / 4)      // 38400
#define W3Q4 (HC3 * HC2 / 4)      // 3840

__global__ void prep_kernel(const float* __restrict__ x,
                            const float* __restrict__ W1,
                            const float* __restrict__ W2,
                            const float* __restrict__ W3) {
    int i = blockIdx.x * 256 + threadIdx.x;
    if (i < N_NODES * 64 / 4) {
        float4 v = ((const float4*)x)[i];
        uint2 p;
        p.x = pack_bf16x2(v.x, v.y);
        p.y = pack_bf16x2(v.z, v.w);
        ((uint2*)g_xq)[i] = p;
    }
    if (2 * i < 6 * N_NODES * 5) {
        g_att[2 * i] = 0.f;
        if (2 * i + 1 < 6 * N_NODES * 5) g_att[2 * i + 1] = 0.f;
    }
    if (i < W1Q4 + W2Q4 + W3Q4) {
        const float4* src;
        uint2* dst;
        int j = i;
        if (j < W1Q4)                { src = (const float4*)W1; dst = (uint2*)g_w1q; }
        else if ((j -= W1Q4) < W2Q4) { src = (const float4*)W2; dst = (uint2*)g_w2q; }
        else { j -= W2Q4;              src = (const float4*)W3; dst = (uint2*)g_w3q; }
        float4 v = src[j];
        uint2 p;
        p.x = pack_bf16x2(v.x, v.y);
        p.y = pack_bf16x2(v.z, v.w);
        dst[j] = p;
    }
}

// ---------------------------------------------------------------------------
// CSR construction
// ---------------------------------------------------------------------------
__global__ void count_kernel(const int* __restrict__ ei) {
    int i = blockIdx.x * blockDim.x + threadIdx.x;
    if (i < N_EDGES) atomicAdd(&g_zero[ei[N_EDGES + i]], 1);
}

__global__ void scan1_kernel() {
    int i = blockIdx.x * 256 + threadIdx.x;
    int lane = threadIdx.x & 31, w = threadIdx.x >> 5;
    int x = (i < N_NODES) ? (g_zero[i] + 1) : 0;
#pragma unroll
    for (int o = 1; o < 32; o <<= 1) {
        int t = __shfl_up_sync(0xffffffffu, x, o);
        if (lane >= o) x += t;
    }
    __shared__ int wsum[8];
    if (lane == 31) wsum[w] = x;
    __syncthreads();
    if (w == 0) {
        int s = (lane < 8) ? wsum[lane] : 0;
#pragma unroll
        for (int o = 1; o < 8; o <<= 1) {
            int t = __shfl_up_sync(0xffffffffu, s, o);
            if (lane >= o) s += t;
        }
        if (lane < 8) wsum[lane] = s;
    }
    __syncthreads();
    int incl = x + ((w > 0) ? wsum[w - 1] : 0);
    if (i < N_NODES) g_rowptr[i + 1] = incl;
    if (threadIdx.x == 255) g_bsum[blockIdx.x] = incl;
}

__global__ void scan3_kernel() {
    __shared__ int s_off;
    int tid = threadIdx.x, lane = tid & 31;
    if (tid < 32) {
        int off = 0;
        for (int j = lane; j < blockIdx.x; j += 32) off += g_bsum[j];
#pragma unroll
        for (int o = 16; o > 0; o >>= 1)
            off += __shfl_xor_sync(0xffffffffu, off, o);
        if (lane == 0) s_off = off;
    }
    __syncthreads();
    int i = blockIdx.x * 256 + tid;
    if (i == 0) g_rowptr[0] = 0;
    if (i < N_NODES) {
        int incl = g_rowptr[i + 1] + s_off;
        g_rowptr[i + 1] = incl;
        g_cursor[i] = incl - (g_zero[i] + 1);
    }
}

__global__ void scatter_kernel(const int* __restrict__ ei) {
    int i = blockIdx.x * blockDim.x + threadIdx.x;
    if (i >= TOT_E) return;
    int src, dst;
    if (i < N_EDGES) { src = ei[i]; dst = ei[N_EDGES + i]; }
    else             { src = dst = i - N_EDGES; }
    int pos = atomicAdd(&g_cursor[dst], 1);
    g_csrc[pos] = src;
}

// ---------------------------------------------------------------------------
// bf16 GEMM (cp.async pipeline) + fused attention-score epilogue.
// C[N,M](bf16) = A[N,K](bf16) * B[M,K]^T(bf16)
// BM=128, BN=128, BK=32; 8 warps (4M x 2N), warp tile 32x64.
// smem row = 32 bf16 = 16 uint32, padded to 20 (80B, 16B aligned).
// ---------------------------------------------------------------------------
#define SROW 20

__device__ __forceinline__ void cp16(uint32_t dst, const void* src, int bytes) {
    asm volatile("cp.async.cg.shared.global [%0], [%1], 16, %2;"
                 :: "r"(dst), "l"(src), "r"(bytes));
}
__device__ __forceinline__ void cp_commit() {
    asm volatile("cp.async.commit_group;");
}
template<int N>
__device__ __forceinline__ void cp_wait() {
    asm volatile("cp.async.wait_group %0;" :: "n"(N));
}

__global__ void __launch_bounds__(256, 2)
gemm_att(const __nv_bfloat16* __restrict__ A, const __nv_bfloat16* __restrict__ B,
         __nv_bfloat16* __restrict__ C,
         const float* __restrict__ att_src, const float* __restrict__ att_dst,
         float* __restrict__ asrc, float* __restrict__ adst,
         int N, int M, int K, int H, int Cc) {
    const int BM = 128, BN = 128, BK = 32;
    __shared__ uint32_t As[2][BM][SROW];
    __shared__ uint32_t Bs[2][BN][SROW];

    int tid  = threadIdx.x;
    int lane = tid & 31;
    int wid  = tid >> 5;
    int wr = (wid & 3) * 32;
    int wc = (wid >> 2) * 64;
    int gid = lane >> 2;
    int tig = lane & 3;

    int blockRow = blockIdx.y * BM;
    int blockCol = blockIdx.x * BN;

    // per-thread cp.async coords: 512 chunks of 16B per tile, 2/thread
    int r0c = (tid + 0)   >> 2, q0 = (tid + 0)   & 3;
    int r1c = (tid + 256) >> 2, q1 = (tid + 256) & 3;

    uint32_t asm0 = (uint32_t)__cvta_generic_to_shared(&As[0][0][0]);
    uint32_t bsm0 = (uint32_t)__cvta_generic_to_shared(&Bs[0][0][0]);
    const uint32_t stage = BM * SROW * 4;   // bytes per stage

    auto issue = [&](int k0, int buf) {
        int ba0 = (blockRow + r0c < N) ? 16 : 0;
        int ba1 = (blockRow + r1c < N) ? 16 : 0;
        int bb0 = (blockCol + r0c < M) ? 16 : 0;
        int bb1 = (blockCol + r1c < M) ? 16 : 0;
        cp16(asm0 + buf * stage + (r0c * SROW + q0 * 4) * 4,
             A + (size_t)(blockRow + r0c) * K + k0 + q0 * 8, ba0);
        cp16(asm0 + buf * stage + (r1c * SROW + q1 * 4) * 4,
             A + (size_t)(blockRow + r1c) * K + k0 + q1 * 8, ba1);
        cp16(bsm0 + buf * stage + (r0c * SROW + q0 * 4) * 4,
             B + (size_t)(blockCol + r0c) * K + k0 + q0 * 8, bb0);
        cp16(bsm0 + buf * stage + (r1c * SROW + q1 * 4) * 4,
             B + (size_t)(blockCol + r1c) * K + k0 + q1 * 8, bb1);
        cp_commit();
    };

    float acc[2][8][4];
#pragma unroll
    for (int mt = 0; mt < 2; mt++)
#pragma unroll
        for (int nt = 0; nt < 8; nt++)
#pragma unroll
            for (int i = 0; i < 4; i++) acc[mt][nt][i] = 0.f;

    int nIt = K / BK;
    issue(0, 0);

    int buf = 0;
    for (int it = 0; it < nIt; it++) {
        if (it + 1 < nIt) {
            issue((it + 1) * BK, buf ^ 1);
            cp_wait<1>();
        } else {
            cp_wait<0>();
        }
        __syncthreads();

#pragma unroll
        for (int ks = 0; ks < 2; ks++) {
            int kb = ks * 8;
            uint32_t a[2][4], b[8][2];
#pragma unroll
            for (int mt = 0; mt < 2; mt++) {
                int r0 = wr + mt * 16;
                a[mt][0] = As[buf][r0 + gid    ][kb + tig    ];
                a[mt][1] = As[buf][r0 + gid + 8][kb + tig    ];
                a[mt][2] = As[buf][r0 + gid    ][kb + tig + 4];
                a[mt][3] = As[buf][r0 + gid + 8][kb + tig + 4];
            }
#pragma unroll
            for (int nt = 0; nt < 8; nt++) {
                int n0 = wc + nt * 8 + gid;
                b[nt][0] = Bs[buf][n0][kb + tig    ];
                b[nt][1] = Bs[buf][n0][kb + tig + 4];
            }
#pragma unroll
            for (int mt = 0; mt < 2; mt++)
#pragma unroll
                for (int nt = 0; nt < 8; nt++) {
                    asm volatile(
                        "mma.sync.aligned.m16n8k16.row.col.f32.bf16.bf16.f32 "
                        "{%0,%1,%2,%3}, {%4,%5,%6,%7}, {%8,%9}, {%0,%1,%2,%3};"
                        : "+f"(acc[mt][nt][0]), "+f"(acc[mt][nt][1]),
                          "+f"(acc[mt][nt][2]), "+f"(acc[mt][nt][3])
                        : "r"(a[mt][0]), "r"(a[mt][1]), "r"(a[mt][2]), "r"(a[mt][3]),
                          "r"(b[nt][0]), "r"(b[nt][1]));
                }
        }
        __syncthreads();
        buf ^= 1;
    }

    // ---- store C + att partials ----
    int h_first = (blockCol + wc) / Cc;
    float psrc[2][2][2] = {};
    float pdst[2][2][2] = {};

#pragma unroll
    for (int mt = 0; mt < 2; mt++) {
#pragma unroll
        for (int nt = 0; nt < 8; nt++) {
            int r0 = blockRow + wr + mt * 16 + gid;
            int c0 = blockCol + wc + nt * 8 + tig * 2;
            if (c0 < M) {
                if (r0 < N)
                    *(uint32_t*)(C + (size_t)r0 * M + c0) =
                        pack_bf16x2(acc[mt][nt][0], acc[mt][nt][1]);
                if (r0 + 8 < N)
                    *(uint32_t*)(C + (size_t)(r0 + 8) * M + c0) =
                        pack_bf16x2(acc[mt][nt][2], acc[mt][nt][3]);
                int hb = (blockCol + wc + nt * 8) / Cc - h_first;
                float a0 = att_src[c0], a1 = att_src[c0 + 1];
                float d0 = att_dst[c0], d1 = att_dst[c0 + 1];
                psrc[mt][0][hb] += acc[mt][nt][0] * a0 + acc[mt][nt][1] * a1;
                psrc[mt][1][hb] += acc[mt][nt][2] * a0 + acc[mt][nt][3] * a1;
                pdst[mt][0][hb] += acc[mt][nt][0] * d0 + acc[mt][nt][1] * d1;
                pdst[mt][1][hb] += acc[mt][nt][2] * d0 + acc[mt][nt][3] * d1;
            }
        }
    }
#pragma unroll
    for (int mt = 0; mt < 2; mt++)
#pragma unroll
        for (int hf = 0; hf < 2; hf++)
#pragma unroll
            for (int bk = 0; bk < 2; bk++) {
                float s = psrc[mt][hf][bk], d = pdst[mt][hf][bk];
                s += __shfl_xor_sync(0xffffffffu, s, 1);
                s += __shfl_xor_sync(0xffffffffu, s, 2);
                d += __shfl_xor_sync(0xffffffffu, d, 1);
                d += __shfl_xor_sync(0xffffffffu, d, 2);
                psrc[mt][hf][bk] = s; pdst[mt][hf][bk] = d;
            }
    if (tig == 0) {
#pragma unroll
        for (int mt = 0; mt < 2; mt++)
#pragma unroll
            for (int hf = 0; hf < 2; hf++) {
                int row = blockRow + wr + mt * 16 + gid + hf * 8;
                if (row >= N) continue;
#pragma unroll
                for (int bk = 0; bk < 2; bk++) {
                    int hidx = h_first + bk;
                    if (hidx < H) {
                        atomicAdd(&asrc[row * H + hidx], psrc[mt][hf][bk]);
                        atomicAdd(&adst[row * H + hidx], pdst[mt][hf][bk]);
                    }
                }
            }
    }
}

// ---------------------------------------------------------------------------
// GAT aggregation, H=5. Single-pass e into smem (deg<=128 fast path).
// ---------------------------------------------------------------------------
template<int C>
__global__ void __launch_bounds__(192)
gat_agg5(const __nv_bfloat16* __restrict__ hfeat,
         const float* __restrict__ asrc,
         const float* __restrict__ adst,
         const float* __restrict__ bias,
         __nv_bfloat16* __restrict__ out) {
    const int HC = 5 * C, NC4 = HC / 4;
    const int EMAX = 128;
    __shared__ float s_e[EMAX * 5];
    __shared__ int   s_src[EMAX];
    __shared__ float s_m[5], s_iz[5], s_ad[5];

    int v = blockIdx.x;
    int tid = threadIdx.x, lane = tid & 31, wid = tid >> 5;
    int base = g_rowptr[v];
    int deg = g_rowptr[v + 1] - base;

    if (tid < 5) s_ad[tid] = adst[v * 5 + tid];
    __syncthreads();

    float4 acc = make_float4(0.f, 0.f, 0.f, 0.f);
    int head = (tid * 4) / C;

    if (deg <= EMAX) {
        for (int idx = tid; idx < deg * 5; idx += 192) {
            int j = idx / 5, hh = idx - j * 5;
            int s = g_csrc[base + j];
            if (hh == 0) s_src[j] = s;
            float e = asrc[s * 5 + hh] + s_ad[hh];
            s_e[idx] = (e > 0.f) ? e : NEG_SLOPE * e;
        }
        __syncthreads();
        if (wid < 5) {
            int h = wid;
            float m = -INFINITY;
            for (int j = lane; j < deg; j += 32)
                m = fmaxf(m, s_e[j * 5 + h]);
#pragma unroll
            for (int o = 16; o > 0; o >>= 1)
                m = fmaxf(m, __shfl_xor_sync(0xffffffffu, m, o));
            float z = 0.f;
            for (int j = lane; j < deg; j += 32) {
                float ex = __expf(s_e[j * 5 + h] - m);
                s_e[j * 5 + h] = ex;
                z += ex;
            }
#pragma unroll
            for (int o = 16; o > 0; o >>= 1)
                z += __shfl_xor_sync(0xffffffffu, z, o);
            if (lane == 0) s_iz[h] = 1.f / (z + EPS_F);
        }
        __syncthreads();
        for (int idx = tid; idx < deg * 5; idx += 192) {
            int hh = idx % 5;
            s_e[idx] *= s_iz[hh];
        }
        __syncthreads();
        if (tid < NC4) {
#pragma unroll 2
            for (int j = 0; j < deg; j++) {
                const uint2* hp = (const uint2*)(hfeat + (size_t)s_src[j] * HC);
                float w = s_e[j * 5 + head];
                uint2 hv = hp[tid];
                float2 lo = __bfloat1622float2(*(__nv_bfloat162*)&hv.x);
                float2 hi = __bfloat1622float2(*(__nv_bfloat162*)&hv.y);
                acc.x += w * lo.x; acc.y += w * lo.y;
                acc.z += w * hi.x; acc.w += w * hi.y;
            }
        }
    } else {
        if (wid < 5) {
            int h = wid;
            float ad = s_ad[h];
            float m = -INFINITY;
            for (int j = lane; j < deg; j += 32) {
                int s = g_csrc[base + j];
                float e = asrc[s * 5 + h] + ad;
                e = (e > 0.f) ? e : NEG_SLOPE * e;
                m = fmaxf(m, e);
            }
#pragma unroll
            for (int o = 16; o > 0; o >>= 1)
                m = fmaxf(m, __shfl_xor_sync(0xffffffffu, m, o));
            float z = 0.f;
            for (int j = lane; j < deg; j += 32) {
                int s = g_csrc[base + j];
                float e = asrc[s * 5 + h] + ad;
                e = (e > 0.f) ? e : NEG_SLOPE * e;
                z += __expf(e - m);
            }
#pragma unroll
            for (int o = 16; o > 0; o >>= 1)
                z += __shfl_xor_sync(0xffffffffu, z, o);
            if (lane == 0) { s_m[h] = m; s_iz[h] = 1.f / (z + EPS_F); }
        }
        __syncthreads();
        for (int j0 = 0; j0 < deg; j0 += EMAX) {
            int ch = min(EMAX, deg - j0);
            for (int idx = tid; idx < ch * 5; idx += 192) {
                int j = idx / 5, hh = idx - j * 5;
                int s = g_csrc[base + j0 + j];
                if (hh == 0) s_src[j] = s;
                float e = asrc[s * 5 + hh] + s_ad[hh];
                e = (e > 0.f) ? e : NEG_SLOPE * e;
                s_e[j * 5 + hh] = __expf(e - s_m[hh]) * s_iz[hh];
            }
            __syncthreads();
            if (tid < NC4) {
                for (int j = 0; j < ch; j++) {
                    const uint2* hp = (const uint2*)(hfeat + (size_t)s_src[j] * HC);
                    float w = s_e[j * 5 + head];
                    uint2 hv = hp[tid];
                    float2 lo = __bfloat1622float2(*(__nv_bfloat162*)&hv.x);
                    float2 hi = __bfloat1622float2(*(__nv_bfloat162*)&hv.y);
                    acc.x += w * lo.x; acc.y += w * lo.y;
                    acc.z += w * hi.x; acc.w += w * hi.y;
                }
            }
            __syncthreads();
        }
    }

    if (tid < NC4) {
        float4 b = ((const float4*)bias)[tid];
        uint2 o;
        o.x = pack_bf16x2(fmaxf(acc.x + b.x, 0.f), fmaxf(acc.y + b.y, 0.f));
        o.y = pack_bf16x2(fmaxf(acc.z + b.z, 0.f), fmaxf(acc.w + b.w, 0.f));
        ((uint2*)(out + (size_t)v * HC))[tid] = o;
    }
}

// ---------------------------------------------------------------------------
// GAT aggregation, H=1, C=32 + fused global_add_pool. warp per node.
// ---------------------------------------------------------------------------
__global__ void __launch_bounds__(256)
gat_agg1_pool(const __nv_bfloat16* __restrict__ hfeat,
              const float* __restrict__ asrc,
              const float* __restrict__ adst,
              const float* __restrict__ bias,
              const int* __restrict__ batch) {
    int wid = threadIdx.x >> 5, lane = threadIdx.x & 31;
    int v = blockIdx.x * 8 + wid;
    if (v >= N_NODES) return;
    int base = g_rowptr[v];
    int deg = g_rowptr[v + 1] - base;
    float ad = adst[v];
    float* pool = (float*)(g_zero + N_NODES);

    float m = -INFINITY;
    for (int j = lane; j < deg; j += 32) {
        int s = g_csrc[base + j];
        float e = asrc[s] + ad;
        e = (e > 0.f) ? e : NEG_SLOPE * e;
        m = fmaxf(m, e);
    }
#pragma unroll
    for (int o = 16; o > 0; o >>= 1)
        m = fmaxf(m, __shfl_xor_sync(0xffffffffu, m, o));
    float z = 0.f;
    for (int j = lane; j < deg; j += 32) {
        int s = g_csrc[base + j];
        float e = asrc[s] + ad;
        e = (e > 0.f) ? e : NEG_SLOPE * e;
        z += __expf(e - m);
    }
#pragma unroll
    for (int o = 16; o > 0; o >>= 1)
        z += __shfl_xor_sync(0xffffffffu, z, o);
    float iz = 1.f / (z + EPS_F);

    float acc = 0.f;
#pragma unroll 2
    for (int j = 0; j < deg; j++) {
        int s = g_csrc[base + j];
        float e = asrc[s] + ad;
        e = (e > 0.f) ? e : NEG_SLOPE * e;
        float w = __expf(e - m) * iz;
        acc += w * __bfloat162float(hfeat[(size_t)s * 32 + lane]);
    }
    float o = fmaxf(acc + bias[lane], 0.f);
    atomicAdd(&pool[batch[v] * 32 + lane], o);
}

// ---------------------------------------------------------------------------
// MLP head
// ---------------------------------------------------------------------------
__global__ void mlp_kernel(const float* __restrict__ lin_w,
                           const float* __restrict__ lin_b,
                           const float* __restrict__ lin2_w,
                           const float* __restrict__ lin2_b,
                           float* __restrict__ out) {
    int g = blockIdx.x;
    __shared__ float sg[32];
    __shared__ float sred[256];
    int tid = threadIdx.x;
    const float* pool = (const float*)(g_zero + N_NODES);
    if (tid < 32) sg[tid] = pool[g * 32 + tid];
    __syncthreads();
    float partial = 0.f;
    for (int u = tid; u < 1024; u += 256) {
        float d = lin_b[u];
        const float* wr = lin_w + u * 32;
#pragma unroll
        for (int c = 0; c < 32; c++) d += sg[c] * wr[c];
        d = fmaxf(d, 0.f);
        partial += d * lin2_w[u];
    }
    sred[tid] = partial;
    __syncthreads();
    for (int s = 128; s > 0; s >>= 1) {
        if (tid < s) sred[tid] += sred[tid + s];
        __syncthreads();
    }
    if (tid == 0) {
        float v = sred[0] + lin2_b[0];
        out[g] = 1.f / (1.f + __expf(-v));
    }
}

// ---------------------------------------------------------------------------
// launch
// ---------------------------------------------------------------------------
extern "C" void kernel_launch(void* const* d_in, const int* in_sizes, int n_in,
                              void* d_out, int out_size) {
    const float* x        = (const float*)d_in[0];
    const float* W1       = (const float*)d_in[1];
    const float* att_s1   = (const float*)d_in[2];
    const float* att_d1   = (const float*)d_in[3];
    const float* b1       = (const float*)d_in[4];
    const float* W2       = (const float*)d_in[5];
    const float* att_s2   = (const float*)d_in[6];
    const float* att_d2   = (const float*)d_in[7];
    const float* b2       = (const float*)d_in[8];
    const float* W3       = (const float*)d_in[9];
    const float* att_s3   = (const float*)d_in[10];
    const float* att_d3   = (const float*)d_in[11];
    const float* b3       = (const float*)d_in[12];
    const float* lin_w    = (const float*)d_in[13];
    const float* lin_b    = (const float*)d_in[14];
    const float* lin2_w   = (const float*)d_in[15];
    const float* lin2_b   = (const float*)d_in[16];
    const int*   ei       = (const int*)d_in[17];
    const int*   batch    = (const int*)d_in[18];
    float* out = (float*)d_out;

    __nv_bfloat16 *xq, *w1q, *w2q, *w3q, *h1, *o1, *h2, *o2, *h3;
    float *attbuf;
    int *zreg;
    cudaGetSymbolAddress((void**)&xq, g_xq);
    cudaGetSymbolAddress((void**)&w1q, g_w1q);
    cudaGetSymbolAddress((void**)&w2q, g_w2q);
    cudaGetSymbolAddress((void**)&w3q, g_w3q);
    cudaGetSymbolAddress((void**)&h1, g_h1);
    cudaGetSymbolAddress((void**)&o1, g_o1);
    cudaGetSymbolAddress((void**)&h2, g_h2);
    cudaGetSymbolAddress((void**)&o2, g_o2);
    cudaGetSymbolAddress((void**)&h3, g_h3);
    cudaGetSymbolAddress((void**)&attbuf, g_att);
    cudaGetSymbolAddress((void**)&zreg, g_zero);

    float* as1 = attbuf;                    float* ad1 = attbuf + N_NODES * 5;
    float* as2 = attbuf + 2 * N_NODES * 5;  float* ad2 = attbuf + 3 * N_NODES * 5;
    float* as3 = attbuf + 4 * N_NODES * 5;  float* ad3 = attbuf + 5 * N_NODES * 5;

    static cudaStream_t s_cs = nullptr;
    static cudaEvent_t ev_fork = nullptr, ev_join = nullptr;
    if (!s_cs) {
        cudaStreamCreateWithFlags(&s_cs, cudaStreamNonBlocking);
        cudaEventCreateWithFlags(&ev_fork, cudaEventDisableTiming);
        cudaEventCreateWithFlags(&ev_join, cudaEventDisableTiming);
    }

    // ---- fork: CSR build on side stream ----
    cudaEventRecord(ev_fork, 0);
    cudaStreamWaitEvent(s_cs, ev_fork, 0);
    cudaMemsetAsync(zreg, 0, (N_NODES + N_GRAPHS * 32) * sizeof(int), s_cs);
    count_kernel<<<(N_EDGES + 255) / 256, 256, 0, s_cs>>>(ei);
    scan1_kernel<<<N_BLK, 256, 0, s_cs>>>();
    scan3_kernel<<<N_BLK, 256, 0, s_cs>>>();
    scatter_kernel<<<(TOT_E + 255) / 256, 256, 0, s_cs>>>(ei);
    cudaEventRecord(ev_join, s_cs);

    // ---- main: prep (x/W conversion + att zero) + GEMM1 ----
    prep_kernel<<<(N_NODES * 64 / 4 + 255) / 256, 256>>>(x, W1, W2, W3);

    const int GY = (N_NODES + 127) / 128;

    gemm_att<<<dim3((HC1 + 127) / 128, GY), 256>>>(
        xq, w1q, h1, att_s1, att_d1, as1, ad1, N_NODES, HC1, 64, 5, 64);

    // ---- join: aggregation needs CSR ----
    cudaStreamWaitEvent(0, ev_join, 0);
    gat_agg5<64><<<N_NODES, 192>>>(h1, as1, ad1, b1, o1);

    gemm_att<<<dim3((HC2 + 127) / 128, GY), 256>>>(
        o1, w2q, h2, att_s2, att_d2, as2, ad2, N_NODES, HC2, HC1, 5, 96);
    gat_agg5<96><<<N_NODES, 192>>>(h2, as2, ad2, b2, o2);

    gemm_att<<<dim3((HC3 + 127) / 128, GY), 256>>>(
        o2, w3q, h3, att_s3, att_d3, as3, ad3, N_NODES, HC3, HC2, 1, 32);
    gat_agg1_pool<<<(N_NODES + 7) / 8, 256>>>(h3, as3, ad3, b3, batch);

    mlp_kernel<<<N_GRAPHS, 256>>>(lin_w, lin_b, lin2_w, lin2_b, out);
}